// round 3
// baseline (speedup 1.0000x reference)
#include <cuda_runtime.h>
#include <math.h>

#define NN 8192
#define EE 65536
#define LAT 128
#define WRS_LD 944
#define UCOLS 816
#define ENVN 48
#define MULN 16
#define SPHN 9
#define QKN 256
#define TOTC 1072
#define EPSF 1e-5f

// ---------- static scratch (no allocation) ----------
__device__ float    g_S[NN * LAT];
__device__ float    g_U[NN * UCOLS];
__device__ float    g_Kn[NN * QKN];
__device__ float    g_dh[NN * LAT];
__device__ float    g_envw[(size_t)EE * ENVN];
__device__ float    g_linw[(size_t)EE * 768];
__device__ float    g_scores[EE * MULN];
__device__ unsigned g_maxb[NN * MULN];
__device__ float    g_den[NN * MULN];
__device__ float    g_dX[NN * MULN * SPHN];

__device__ __forceinline__ unsigned fenc(float f) {
    unsigned u = __float_as_uint(f);
    return (u & 0x80000000u) ? ~u : (u | 0x80000000u);
}
__device__ __forceinline__ float fdec(unsigned u) {
    return (u & 0x80000000u) ? __uint_as_float(u & 0x7FFFFFFFu)
                             : __uint_as_float(~u);
}

__global__ void init_kernel() {
    int i = blockIdx.x * blockDim.x + threadIdx.x;
    int stride = gridDim.x * blockDim.x;
    for (int t = i; t < NN * LAT; t += stride) g_dh[t] = 0.f;
    for (int t = i; t < EE * MULN; t += stride) g_scores[t] = 0.f;
    for (int t = i; t < NN * MULN; t += stride) { g_den[t] = 0.f; g_maxb[t] = 0u; }
    for (int t = i; t < NN * MULN * SPHN; t += stride) g_dX[t] = 0.f;
}

// ---------- generic K=128 SGEMM, 128x128 tile, 256 thr, 8x8/thr ----------
template <bool SILU>
__global__ void __launch_bounds__(256) sgemm_k128(
    const float* __restrict__ A, const float* __restrict__ B,
    float* __restrict__ C, int ncols, int ldb, int ldc)
{
    __shared__ float As[16][132];
    __shared__ float Bs[16][132];
    const int bm = blockIdx.y << 7;
    const int bn = blockIdx.x << 7;
    const int tid = threadIdx.x;
    const int tx = tid & 15, ty = tid >> 4;
    float acc[8][8];
#pragma unroll
    for (int i = 0; i < 8; i++)
#pragma unroll
        for (int j = 0; j < 8; j++) acc[i][j] = 0.f;

    for (int k0 = 0; k0 < 128; k0 += 16) {
#pragma unroll
        for (int hh = 0; hh < 2; hh++) {
            int t = tid + hh * 256;
            int r = t >> 2, kq = (t & 3) << 2;
            float4 av = *(const float4*)(A + (size_t)(bm + r) * 128 + k0 + kq);
            As[kq + 0][r] = av.x; As[kq + 1][r] = av.y;
            As[kq + 2][r] = av.z; As[kq + 3][r] = av.w;
        }
#pragma unroll
        for (int hh = 0; hh < 2; hh++) {
            int t = tid + hh * 256;
            int kr = t >> 5, c4 = (t & 31) << 2;
            int c = bn + c4;
            float4 bv = make_float4(0.f, 0.f, 0.f, 0.f);
            if (c < ncols) bv = *(const float4*)(B + (size_t)(k0 + kr) * ldb + c);
            *(float4*)&Bs[kr][c4] = bv;
        }
        __syncthreads();
#pragma unroll
        for (int kk = 0; kk < 16; kk++) {
            float a[8], b[8];
            *(float4*)(a + 0) = *(const float4*)&As[kk][ty << 2];
            *(float4*)(a + 4) = *(const float4*)&As[kk][64 + (ty << 2)];
            *(float4*)(b + 0) = *(const float4*)&Bs[kk][tx << 2];
            *(float4*)(b + 4) = *(const float4*)&Bs[kk][64 + (tx << 2)];
#pragma unroll
            for (int i = 0; i < 8; i++)
#pragma unroll
                for (int j = 0; j < 8; j++) acc[i][j] += a[i] * b[j];
        }
        __syncthreads();
    }
#pragma unroll
    for (int ih = 0; ih < 2; ih++)
#pragma unroll
    for (int i = 0; i < 4; i++) {
        int row = bm + ih * 64 + (ty << 2) + i;
#pragma unroll
        for (int jh = 0; jh < 2; jh++) {
            int c = bn + jh * 64 + (tx << 2);
            if (c < ncols) {
                float v0 = acc[ih * 4 + i][jh * 4 + 0];
                float v1 = acc[ih * 4 + i][jh * 4 + 1];
                float v2 = acc[ih * 4 + i][jh * 4 + 2];
                float v3 = acc[ih * 4 + i][jh * 4 + 3];
                if (SILU) {
                    v0 = v0 / (1.f + expf(-v0));
                    v1 = v1 / (1.f + expf(-v1));
                    v2 = v2 / (1.f + expf(-v2));
                    v3 = v3 / (1.f + expf(-v3));
                }
                *(float4*)(C + (size_t)row * ldc + c) = make_float4(v0, v1, v2, v3);
            }
        }
    }
}

// ---------- edge GEMM: t_ij @ [W_rs[:,:816] | W_query], fused epilogue ----------
__global__ void __launch_bounds__(256) edge_gemm_kernel(
    const float* __restrict__ T, const float* __restrict__ Wrs,
    const float* __restrict__ Wq, const int* __restrict__ ectr,
    const int* __restrict__ enb)
{
    __shared__ float As[16][132];
    __shared__ float Bs[16][132];
    __shared__ int s_j[128], s_c[128];
    const int bm = blockIdx.y << 7;
    const int bn = blockIdx.x << 7;
    const int tid = threadIdx.x;
    if (tid < 128) { s_j[tid] = enb[bm + tid]; s_c[tid] = ectr[bm + tid]; }
    const int tx = tid & 15, ty = tid >> 4;
    float acc[8][8];
#pragma unroll
    for (int i = 0; i < 8; i++)
#pragma unroll
        for (int j = 0; j < 8; j++) acc[i][j] = 0.f;

    for (int k0 = 0; k0 < 128; k0 += 16) {
#pragma unroll
        for (int hh = 0; hh < 2; hh++) {
            int t = tid + hh * 256;
            int r = t >> 2, kq = (t & 3) << 2;
            float4 av = *(const float4*)(T + (size_t)(bm + r) * 128 + k0 + kq);
            As[kq + 0][r] = av.x; As[kq + 1][r] = av.y;
            As[kq + 2][r] = av.z; As[kq + 3][r] = av.w;
        }
#pragma unroll
        for (int hh = 0; hh < 2; hh++) {
            int t = tid + hh * 256;
            int kr = t >> 5, c4 = (t & 31) << 2;
            int c = bn + c4;
            float4 bv = make_float4(0.f, 0.f, 0.f, 0.f);
            if (c < UCOLS)      bv = *(const float4*)(Wrs + (size_t)(k0 + kr) * WRS_LD + c);
            else if (c < TOTC)  bv = *(const float4*)(Wq + (size_t)(k0 + kr) * QKN + (c - UCOLS));
            *(float4*)&Bs[kr][c4] = bv;
        }
        __syncthreads();
#pragma unroll
        for (int kk = 0; kk < 16; kk++) {
            float a[8], b[8];
            *(float4*)(a + 0) = *(const float4*)&As[kk][ty << 2];
            *(float4*)(a + 4) = *(const float4*)&As[kk][64 + (ty << 2)];
            *(float4*)(b + 0) = *(const float4*)&Bs[kk][tx << 2];
            *(float4*)(b + 4) = *(const float4*)&Bs[kk][64 + (tx << 2)];
#pragma unroll
            for (int i = 0; i < 8; i++)
#pragma unroll
                for (int j = 0; j < 8; j++) acc[i][j] += a[i] * b[j];
        }
        __syncthreads();
    }

#pragma unroll
    for (int ih = 0; ih < 2; ih++)
#pragma unroll
    for (int i = 0; i < 4; i++) {
        int r = ih * 64 + (ty << 2) + i;
        int e = bm + r;
        int j = s_j[r], ct = s_c[r];
#pragma unroll
        for (int jh = 0; jh < 2; jh++) {
            int cb = bn + jh * 64 + (tx << 2);
            float v0 = acc[ih * 4 + i][jh * 4 + 0];
            float v1 = acc[ih * 4 + i][jh * 4 + 1];
            float v2 = acc[ih * 4 + i][jh * 4 + 2];
            float v3 = acc[ih * 4 + i][jh * 4 + 3];
            if (cb < UCOLS) {
                float4 uv = *(const float4*)(g_U + (size_t)j * UCOLS + cb);
                v0 *= uv.x; v1 *= uv.y; v2 *= uv.z; v3 *= uv.w;
                if (cb < 128) {
                    atomicAdd(&g_dh[ct * 128 + cb + 0], v0);
                    atomicAdd(&g_dh[ct * 128 + cb + 1], v1);
                    atomicAdd(&g_dh[ct * 128 + cb + 2], v2);
                    atomicAdd(&g_dh[ct * 128 + cb + 3], v3);
                }
                if (cb < ENVN) {
                    *(float4*)(g_envw + (size_t)e * ENVN + cb) = make_float4(v0, v1, v2, v3);
                } else {
                    *(float4*)(g_linw + (size_t)e * 768 + (cb - ENVN)) = make_float4(v0, v1, v2, v3);
                }
            } else if (cb < TOTC) {
                float4 kv = *(const float4*)(g_Kn + (size_t)j * QKN + (cb - UCOLS));
                float qs = v0 * kv.x + v1 * kv.y + v2 * kv.z + v3 * kv.w;
                atomicAdd(&g_scores[e * 16 + ((cb - UCOLS) >> 4)], 4.0f * qs);
            }
        }
    }
}

// ---------- scatter softmax ----------
__global__ void smax_kernel(const int* __restrict__ ectr) {
    int idx = blockIdx.x * blockDim.x + threadIdx.x;
    int e = idx >> 4, m = idx & 15;
    atomicMax(&g_maxb[ectr[e] * 16 + m], fenc(g_scores[idx]));
}

__global__ void sexp_kernel(const int* __restrict__ ectr) {
    int idx = blockIdx.x * blockDim.x + threadIdx.x;
    int e = idx >> 4, m = idx & 15;
    int ct = ectr[e];
    float mx = fdec(g_maxb[ct * 16 + m]);
    float ex = expf(g_scores[idx] - mx);
    g_scores[idx] = ex;
    atomicAdd(&g_den[ct * 16 + m], ex);
}

// ---------- per-edge equivariant update, warp/edge ----------
__global__ void __launch_bounds__(256) edge_apply_kernel(
    const float* __restrict__ sph, const float* __restrict__ Xin,
    const int* __restrict__ ectr, const int* __restrict__ enb)
{
    __shared__ float sXj[8][144];
    __shared__ float sal[8][16];
    const int warp = threadIdx.x >> 5;
    const int lane = threadIdx.x & 31;
    const int e = blockIdx.x * 8 + warp;
    const int j = enb[e];
    const int ct = ectr[e];
    for (int t = lane; t < 144; t += 32) sXj[warp][t] = Xin[(size_t)j * 144 + t];
    if (lane < 16) {
        float ex = g_scores[e * 16 + lane];
        float dn = g_den[ct * 16 + lane];
        sal[warp][lane] = ex / (dn + 1e-20f);
    }
    __syncwarp();
    const float* lw = g_linw + (size_t)e * 768;
    const float* ew = g_envw + (size_t)e * ENVN;
    const float* sp = sph + (size_t)e * 9;
    const int u = lane & 15;
    const float al = sal[warp][u];
    float wr[16];
    if (lane < 16) {
        // irrep 0 (d=0)
#pragma unroll
        for (int v = 0; v < 16; v++) wr[v] = lw[u * 16 + v];
        float a0 = 0.f;
#pragma unroll
        for (int v = 0; v < 16; v++) a0 += wr[v] * sXj[warp][v * 9 + 0];
        atomicAdd(&g_dX[(size_t)ct * 144 + u * 9 + 0],
                  (sp[0] * ew[u] + 0.25f * a0) * al);
        // irrep 1 (d=1..3)
#pragma unroll
        for (int v = 0; v < 16; v++) wr[v] = lw[256 + u * 16 + v];
#pragma unroll
        for (int d = 1; d <= 3; d++) {
            float a = 0.f;
#pragma unroll
            for (int v = 0; v < 16; v++) a += wr[v] * sXj[warp][v * 9 + d];
            atomicAdd(&g_dX[(size_t)ct * 144 + u * 9 + d],
                      (sp[d] * ew[16 + u] + 0.25f * a) * al);
        }
        // irrep 2 (d=4)
#pragma unroll
        for (int v = 0; v < 16; v++) wr[v] = lw[512 + u * 16 + v];
        float a4 = 0.f;
#pragma unroll
        for (int v = 0; v < 16; v++) a4 += wr[v] * sXj[warp][v * 9 + 4];
        atomicAdd(&g_dX[(size_t)ct * 144 + u * 9 + 4],
                  (sp[4] * ew[32 + u] + 0.25f * a4) * al);
    } else {
        // irrep 2 (d=5..8)
#pragma unroll
        for (int v = 0; v < 16; v++) wr[v] = lw[512 + u * 16 + v];
#pragma unroll
        for (int d = 5; d <= 8; d++) {
            float a = 0.f;
#pragma unroll
            for (int v = 0; v < 16; v++) a += wr[v] * sXj[warp][v * 9 + d];
            atomicAdd(&g_dX[(size_t)ct * 144 + u * 9 + d],
                      (sp[d] * ew[32 + u] + 0.25f * a) * al);
        }
    }
}

// ---------- node finalize: layernorm(h + dh) ----------
__global__ void node_h_kernel(const float* __restrict__ h,
                              const float* __restrict__ gam,
                              const float* __restrict__ bet,
                              float* __restrict__ out)
{
    int n = blockIdx.x * 8 + (threadIdx.x >> 5);
    int lane = threadIdx.x & 31;
    float4 hv = *(const float4*)(h + (size_t)n * 128 + lane * 4);
    float4 dv = *(const float4*)(g_dh + (size_t)n * 128 + lane * 4);
    float v[4] = {hv.x + dv.x, hv.y + dv.y, hv.z + dv.z, hv.w + dv.w};
    float s = 0.f, sq = 0.f;
#pragma unroll
    for (int k = 0; k < 4; k++) { s += v[k]; sq += v[k] * v[k]; }
#pragma unroll
    for (int o = 16; o; o >>= 1) {
        s  += __shfl_xor_sync(0xFFFFFFFFu, s, o);
        sq += __shfl_xor_sync(0xFFFFFFFFu, sq, o);
    }
    float mu = s * (1.f / 128.f);
    float var = sq * (1.f / 128.f) - mu * mu;
    float inv = rsqrtf(var + EPSF);
    float4 ov;
    ov.x = (v[0] - mu) * inv * gam[lane * 4 + 0] + bet[lane * 4 + 0];
    ov.y = (v[1] - mu) * inv * gam[lane * 4 + 1] + bet[lane * 4 + 1];
    ov.z = (v[2] - mu) * inv * gam[lane * 4 + 2] + bet[lane * 4 + 2];
    ov.w = (v[3] - mu) * inv * gam[lane * 4 + 3] + bet[lane * 4 + 3];
    *(float4*)(out + (size_t)n * 128 + lane * 4) = ov;
}

// ---------- node finalize: so3_layernorm(X + dX) ----------
__global__ void node_X_kernel(const float* __restrict__ Xin,
                              float* __restrict__ out)
{
    int n = blockIdx.x * 8 + (threadIdx.x >> 5);
    int lane = threadIdx.x & 31;
    float vals[5];
    float s0 = 0.f, s1 = 0.f, s2 = 0.f;
    int k = 0;
    for (int t = lane; t < 144; t += 32, k++) {
        float v = Xin[(size_t)n * 144 + t] + g_dX[(size_t)n * 144 + t];
        vals[k] = v;
        int s = t % 9;
        if (s == 0) s0 += v * v;
        else if (s < 4) s1 += v * v;
        else s2 += v * v;
    }
#pragma unroll
    for (int o = 16; o; o >>= 1) {
        s0 += __shfl_xor_sync(0xFFFFFFFFu, s0, o);
        s1 += __shfl_xor_sync(0xFFFFFFFFu, s1, o);
        s2 += __shfl_xor_sync(0xFFFFFFFFu, s2, o);
    }
    float i0 = rsqrtf(s0 * (1.f / 16.f) + EPSF);
    float i1 = rsqrtf(s1 * (1.f / 48.f) + EPSF);
    float i2 = rsqrtf(s2 * (1.f / 80.f) + EPSF);
    k = 0;
    for (int t = lane; t < 144; t += 32, k++) {
        int s = t % 9;
        float inv = (s == 0) ? i0 : ((s < 4) ? i1 : i2);
        out[(size_t)n * 144 + t] = vals[k] * inv;
    }
}

// ---------- copy t_ij to output tail ----------
__global__ void copy_t_kernel(const float* __restrict__ src, float* __restrict__ dst) {
    size_t i = (size_t)blockIdx.x * blockDim.x + threadIdx.x;
    ((float4*)dst)[i] = ((const float4*)src)[i];
}

extern "C" void kernel_launch(void* const* d_in, const int* in_sizes, int n_in,
                              void* d_out, int out_size) {
    const float* h      = (const float*)d_in[0];
    const float* X      = (const float*)d_in[1];
    const float* t_ij   = (const float*)d_in[2];
    const float* sph    = (const float*)d_in[3];
    const int*   ectr   = (const int*)d_in[5];
    const int*   enb    = (const int*)d_in[6];
    const float* W_rs   = (const float*)d_in[7];
    const float* W1     = (const float*)d_in[8];
    const float* W2     = (const float*)d_in[9];
    const float* gam    = (const float*)d_in[10];
    const float* bet    = (const float*)d_in[11];
    const float* W_q    = (const float*)d_in[12];
    const float* W_k    = (const float*)d_in[13];
    float* out = (float*)d_out;

    // CRITICAL: __device__ globals must be resolved to device addresses before
    // being passed as kernel arguments (host shadow address is NOT the device
    // address; on GB300/ATS it silently reads/writes host memory).
    void *pS = nullptr, *pU = nullptr, *pK = nullptr;
    cudaGetSymbolAddress(&pS, g_S);
    cudaGetSymbolAddress(&pU, g_U);
    cudaGetSymbolAddress(&pK, g_Kn);
    float* dS = (float*)pS;
    float* dU = (float*)pU;
    float* dK = (float*)pK;

    init_kernel<<<2048, 256>>>();
    sgemm_k128<true ><<<dim3(1, 64), 256>>>(h,  W1,  dS, 128, 128, 128);
    sgemm_k128<false><<<dim3(7, 64), 256>>>(dS, W2,  dU, UCOLS, WRS_LD, UCOLS);
    sgemm_k128<false><<<dim3(2, 64), 256>>>(h,  W_k, dK, QKN, QKN, QKN);
    edge_gemm_kernel<<<dim3(9, 512), 256>>>(t_ij, W_rs, W_q, ectr, enb);
    smax_kernel<<<EE * 16 / 256, 256>>>(ectr);
    sexp_kernel<<<EE * 16 / 256, 256>>>(ectr);
    edge_apply_kernel<<<EE / 8, 256>>>(sph, X, ectr, enb);
    node_h_kernel<<<NN / 8, 256>>>(h, gam, bet, out);
    node_X_kernel<<<NN / 8, 256>>>(X, out + (size_t)NN * 128);
    copy_t_kernel<<<(EE * 128 / 4) / 256, 256>>>(t_ij, out + (size_t)NN * 128 + (size_t)NN * 144);
}